// round 3
// baseline (speedup 1.0000x reference)
#include <cuda_runtime.h>
#include <math.h>

#define TPB 256
#define EPB (TPB/4)     // 64 elements per block

typedef unsigned long long u64;

__device__ __forceinline__ u64 pk2(float x, float y) {
    u64 r; asm("mov.b64 %0, {%1,%2};" : "=l"(r) : "f"(x), "f"(y)); return r;
}
__device__ __forceinline__ void upk2(u64 v, float& x, float& y) {
    asm("mov.b64 {%0,%1}, %2;" : "=f"(x), "=f"(y) : "l"(v));
}
__device__ __forceinline__ u64 ffma2(u64 a, u64 b, u64 c) {
    u64 d; asm("fma.rn.f32x2 %0, %1, %2, %3;" : "=l"(d) : "l"(a), "l"(b), "l"(c)); return d;
}
__device__ __forceinline__ float gelu_f(float x) {
    return 0.5f * x * (1.0f + erff(x * 0.70710678118654752440f));
}

// Forward kinematics for the 7-DOF Panda chain -> 7 keypoint positions.
__device__ __forceinline__ void fk_eval(const float th[7], float kp[21]) {
    const float FR[7][9] = {
        {1,0,0,  0,1,0,   0,0,1},
        {1,0,0,  0,0,1,   0,-1,0},
        {1,0,0,  0,0,-1,  0,1,0},
        {1,0,0,  0,0,-1,  0,1,0},
        {1,0,0,  0,0,1,   0,-1,0},
        {1,0,0,  0,0,-1,  0,1,0},
        {1,0,0,  0,0,-1,  0,1,0}
    };
    const float FT[7][3] = {
        {0.f,0.f,0.333f},{0.f,0.f,0.f},{0.f,-0.316f,0.f},{0.0825f,0.f,0.f},
        {-0.0825f,0.384f,0.f},{0.f,0.f,0.f},{0.088f,0.f,0.f}
    };
    float r[9] = {1,0,0, 0,1,0, 0,0,1};
    float t[3] = {0,0,0};
    kp[0] = 0.f; kp[1] = 0.f; kp[2] = 0.f;
    int w = 3;
    #pragma unroll
    for (int i = 0; i < 7; i++) {
        float s, c; sincosf(th[i], &s, &c);
        float sr[9];
        sr[0] =  FR[i][0]*c + FR[i][1]*s;  sr[1] = -FR[i][0]*s + FR[i][1]*c;  sr[2] = FR[i][2];
        sr[3] =  FR[i][3]*c + FR[i][4]*s;  sr[4] = -FR[i][3]*s + FR[i][4]*c;  sr[5] = FR[i][5];
        sr[6] =  FR[i][6]*c + FR[i][7]*s;  sr[7] = -FR[i][6]*s + FR[i][7]*c;  sr[8] = FR[i][8];
        float nt0 = r[0]*FT[i][0] + r[1]*FT[i][1] + r[2]*FT[i][2] + t[0];
        float nt1 = r[3]*FT[i][0] + r[4]*FT[i][1] + r[5]*FT[i][2] + t[1];
        float nt2 = r[6]*FT[i][0] + r[7]*FT[i][1] + r[8]*FT[i][2] + t[2];
        float nr[9];
        #pragma unroll
        for (int a = 0; a < 3; a++)
            #pragma unroll
            for (int bq = 0; bq < 3; bq++)
                nr[a*3+bq] = r[a*3+0]*sr[bq] + r[a*3+1]*sr[3+bq] + r[a*3+2]*sr[6+bq];
        #pragma unroll
        for (int q = 0; q < 9; q++) r[q] = nr[q];
        t[0] = nt0; t[1] = nt1; t[2] = nt2;
        if (i == 1 || i == 2 || i == 3 || i == 5 || i == 6) {
            kp[w] = t[0]; kp[w+1] = t[1]; kp[w+2] = t[2]; w += 3;
        }
    }
    kp[18] = t[0] + r[2]*0.107f;
    kp[19] = t[1] + r[5]*0.107f;
    kp[20] = t[2] + r[8]*0.107f;
}

// Shared memory layout (float offsets) — weights only, no activation staging.
#define OFF_W1   0        // 28*128
#define OFF_W2   3584     // 128*128
#define OFF_W3   19968    // 128*8 (padded)
#define OFF_B1   20992
#define OFF_G1   21120
#define OFF_BE1  21248
#define OFF_B2   21376
#define OFF_G2   21504
#define OFF_BE2  21632
#define OFF_B3   21760
#define SMEM_FLOATS (OFF_B3 + 8)

__global__ void __launch_bounds__(TPB, 2)
irm_kernel(const float* __restrict__ ang, const float* __restrict__ tgt,
           const float* __restrict__ Kc,  const float* __restrict__ Re,
           const float* __restrict__ te,  const int* __restrict__ vmk,
           const float* __restrict__ W1,  const float* __restrict__ b1,
           const float* __restrict__ g1,  const float* __restrict__ be1,
           const float* __restrict__ W2,  const float* __restrict__ b2,
           const float* __restrict__ g2,  const float* __restrict__ be2,
           const float* __restrict__ W3,  const float* __restrict__ b3,
           const float* __restrict__ slog, float* __restrict__ out, int Bn)
{
    extern __shared__ float sm[];
    float* sW1  = sm + OFF_W1;
    float* sW2  = sm + OFF_W2;
    float* sW3  = sm + OFF_W3;
    float* sb1  = sm + OFF_B1;
    float* sg1  = sm + OFF_G1;
    float* sbe1 = sm + OFF_BE1;
    float* sb2  = sm + OFF_B2;
    float* sg2  = sm + OFF_G2;
    float* sbe2 = sm + OFF_BE2;
    float* sb3  = sm + OFF_B3;

    const int tid = threadIdx.x;
    for (int i = tid; i < 3584;  i += TPB) sW1[i] = W1[i];
    for (int i = tid; i < 16384; i += TPB) sW2[i] = W2[i];
    for (int i = tid; i < 1024;  i += TPB) {
        int k = i >> 3, j = i & 7;
        sW3[i] = (j < 7) ? W3[k*7 + j] : 0.f;
    }
    if (tid < 128) {
        sb1[tid]  = b1[tid];  sg1[tid] = g1[tid];  sbe1[tid] = be1[tid];
        sb2[tid]  = b2[tid];  sg2[tid] = g2[tid];  sbe2[tid] = be2[tid];
    }
    if (tid < 8) sb3[tid] = (tid < 7) ? b3[tid] : 0.f;
    __syncthreads();

    const int q  = tid & 3;            // quad lane: owns hidden units [32q, 32q+32)
    const int el = tid >> 2;           // element within block
    int b = blockIdx.x * EPB + el;
    const bool valid = (b < Bn);
    if (b >= Bn) b = Bn - 1;           // clamp so shuffles stay uniform

    float th[7];
    #pragma unroll
    for (int j = 0; j < 7; j++) th[j] = ang[(size_t)b*7 + j];
    const float vm = (vmk[b] != 0) ? 1.f : 0.f;

    const float LO[7] = {-2.8973f,-1.7628f,-2.8973f,-3.0718f,-2.8973f,-0.0175f,-2.8973f};
    const float HI[7] = { 2.8973f, 1.7628f, 2.8973f,-0.0698f, 2.8973f, 3.7525f, 2.8973f};

    float kp[21];
    fk_eval(th, kp);

    float* outA = out + (size_t)28 * Bn;   // all_angles (4,B,7)
    float* outK = out + (size_t)56 * Bn;   // all_kp     (4,B,7,3)

    if (q == 0 && valid) {
        #pragma unroll
        for (int j = 0; j < 7; j++)  outA[(size_t)b*7 + j]  = th[j];
        #pragma unroll
        for (int j = 0; j < 21; j++) outK[(size_t)b*21 + j] = kp[j];
    }

    for (int it = 0; it < 3; it++) {
        // ---- features (redundant across quad; per-element camera data reloaded) ----
        float x[28];
        {
            float Rm[9], Km[9], tv[3];
            #pragma unroll
            for (int j = 0; j < 9; j++) { Rm[j] = Re[(size_t)b*9 + j]; Km[j] = Kc[(size_t)b*9 + j]; }
            #pragma unroll
            for (int j = 0; j < 3; j++) tv[j] = te[(size_t)b*3 + j];
            #pragma unroll
            for (int k = 0; k < 7; k++) {
                float px = kp[3*k], py = kp[3*k+1], pz = kp[3*k+2];
                float cx = Rm[0]*px + Rm[1]*py + Rm[2]*pz + tv[0];
                float cy = Rm[3]*px + Rm[4]*py + Rm[5]*pz + tv[1];
                float cz = Rm[6]*px + Rm[7]*py + Rm[8]*pz + tv[2];
                float z  = fmaxf(cz, 1e-6f);
                float inv = 1.0f / z;
                float nx = cx*inv, ny = cy*inv, nz = cz*inv;
                float u = Km[0]*nx + Km[1]*ny + Km[2]*nz;
                float v = Km[3]*nx + Km[4]*ny + Km[5]*nz;
                float dx = (tgt[(size_t)b*14 + 2*k]   - u) * vm;
                float dy = (tgt[(size_t)b*14 + 2*k+1] - v) * vm;
                x[2*k] = dx; x[2*k+1] = dy;
                x[21+k] = sqrtf(dx*dx + dy*dy);
            }
            #pragma unroll
            for (int j = 0; j < 7; j++) x[14+j] = th[j];
        }

        // ---- GEMM1: (28)->(32 per thread), f32x2 packed ----
        u64 acc[16];
        {
            const u64* pb1 = (const u64*)sb1 + q*16;
            #pragma unroll
            for (int i = 0; i < 16; i++) acc[i] = pb1[i];
            const ulonglong2* W1q = (const ulonglong2*)sW1;
            #pragma unroll
            for (int k = 0; k < 28; k++) {
                u64 xx = pk2(x[k], x[k]);
                const ulonglong2* wrow = W1q + k*32 + q*8;
                #pragma unroll
                for (int i = 0; i < 8; i++) {
                    ulonglong2 w = wrow[i];
                    acc[2*i]   = ffma2(xx, w.x, acc[2*i]);
                    acc[2*i+1] = ffma2(xx, w.y, acc[2*i+1]);
                }
            }
        }

        // ---- GELU + LN1 (quad reduction), normalize into h regs ----
        float h[32];
        {
            #pragma unroll
            for (int i = 0; i < 16; i++) upk2(acc[i], h[2*i], h[2*i+1]);
            float sum = 0.f, sq = 0.f;
            #pragma unroll 4
            for (int j = 0; j < 32; j++) {
                float a = gelu_f(h[j]);
                h[j] = a; sum += a; sq += a*a;
            }
            sum += __shfl_xor_sync(0xffffffffu, sum, 1);
            sum += __shfl_xor_sync(0xffffffffu, sum, 2);
            sq  += __shfl_xor_sync(0xffffffffu, sq, 1);
            sq  += __shfl_xor_sync(0xffffffffu, sq, 2);
            float mu   = sum * (1.f/128.f);
            float var  = sq  * (1.f/128.f) - mu*mu;
            float rstd = rsqrtf(var + 1e-5f);
            #pragma unroll
            for (int j = 0; j < 32; j++)
                h[j] = (h[j] - mu) * rstd * sg1[q*32+j] + sbe1[q*32+j];
        }

        // ---- GEMM2: (128)->(32 per thread); h[k] via quad shuffle broadcast ----
        {
            const u64* pb2 = (const u64*)sb2 + q*16;
            #pragma unroll
            for (int i = 0; i < 16; i++) acc[i] = pb2[i];
            const ulonglong2* W2q = (const ulonglong2*)sW2;
            #pragma unroll 1
            for (int o = 0; o < 4; o++) {
                #pragma unroll
                for (int j = 0; j < 32; j++) {
                    float v = __shfl_sync(0xffffffffu, h[j], o, 4);
                    u64 hh = pk2(v, v);
                    const ulonglong2* wrow = W2q + (o*32 + j)*32 + q*8;
                    #pragma unroll
                    for (int i = 0; i < 8; i++) {
                        ulonglong2 w = wrow[i];
                        acc[2*i]   = ffma2(hh, w.x, acc[2*i]);
                        acc[2*i+1] = ffma2(hh, w.y, acc[2*i+1]);
                    }
                }
            }
        }

        // ---- GELU + LN2, normalize in regs ----
        {
            #pragma unroll
            for (int i = 0; i < 16; i++) upk2(acc[i], h[2*i], h[2*i+1]);
            float sum = 0.f, sq = 0.f;
            #pragma unroll 4
            for (int j = 0; j < 32; j++) {
                float a = gelu_f(h[j]);
                h[j] = a; sum += a; sq += a*a;
            }
            sum += __shfl_xor_sync(0xffffffffu, sum, 1);
            sum += __shfl_xor_sync(0xffffffffu, sum, 2);
            sq  += __shfl_xor_sync(0xffffffffu, sq, 1);
            sq  += __shfl_xor_sync(0xffffffffu, sq, 2);
            float mu   = sum * (1.f/128.f);
            float var  = sq  * (1.f/128.f) - mu*mu;
            float rstd = rsqrtf(var + 1e-5f);
            #pragma unroll
            for (int j = 0; j < 32; j++)
                h[j] = (h[j] - mu) * rstd * sg2[q*32+j] + sbe2[q*32+j];
        }

        // ---- GEMM3: partial (32)->(7), quad reduce ----
        float a3[7] = {0,0,0,0,0,0,0};
        #pragma unroll
        for (int j = 0; j < 32; j++) {
            float v = h[j];
            const float4* w4 = (const float4*)(sW3 + (q*32+j)*8);
            float4 wa = w4[0], wb = w4[1];
            a3[0] += v*wa.x; a3[1] += v*wa.y; a3[2] += v*wa.z; a3[3] += v*wa.w;
            a3[4] += v*wb.x; a3[5] += v*wb.y; a3[6] += v*wb.z;
        }
        #pragma unroll
        for (int c = 0; c < 7; c++) {
            a3[c] += __shfl_xor_sync(0xffffffffu, a3[c], 1);
            a3[c] += __shfl_xor_sync(0xffffffffu, a3[c], 2);
            a3[c] += sb3[c];
        }

        float ss = 1.f / (1.f + expf(-slog[it]));
        #pragma unroll
        for (int j = 0; j < 7; j++) {
            float nv = th[j] + ss * a3[j];
            th[j] = fminf(fmaxf(nv, LO[j]), HI[j]);
        }
        fk_eval(th, kp);

        const size_t w = (size_t)(it + 1);
        if (q == 0 && valid) {
            #pragma unroll
            for (int j = 0; j < 7; j++)  outA[w*(size_t)Bn*7  + (size_t)b*7  + j] = th[j];
            #pragma unroll
            for (int j = 0; j < 21; j++) outK[w*(size_t)Bn*21 + (size_t)b*21 + j] = kp[j];
        }
    }

    if (q == 0 && valid) {
        #pragma unroll
        for (int j = 0; j < 7; j++)  out[(size_t)b*7 + j] = th[j];
        #pragma unroll
        for (int j = 0; j < 21; j++) out[(size_t)7*Bn + (size_t)b*21 + j] = kp[j];
    }
}

extern "C" void kernel_launch(void* const* d_in, const int* in_sizes, int n_in,
                              void* d_out, int out_size)
{
    const float* ang  = (const float*)d_in[0];
    const float* tgt  = (const float*)d_in[1];
    const float* Kc   = (const float*)d_in[2];
    const float* Re   = (const float*)d_in[4];
    const float* te   = (const float*)d_in[5];
    const int*   vmk  = (const int*)d_in[6];
    const float* W1   = (const float*)d_in[7];
    const float* b1   = (const float*)d_in[8];
    const float* g1   = (const float*)d_in[9];
    const float* be1  = (const float*)d_in[10];
    const float* W2   = (const float*)d_in[11];
    const float* b2   = (const float*)d_in[12];
    const float* g2   = (const float*)d_in[13];
    const float* be2  = (const float*)d_in[14];
    const float* W3   = (const float*)d_in[15];
    const float* b3   = (const float*)d_in[16];
    const float* slog = (const float*)d_in[17];

    const int Bn = in_sizes[0] / 7;
    const size_t smem = (size_t)SMEM_FLOATS * sizeof(float);

    cudaFuncSetAttribute(irm_kernel, cudaFuncAttributeMaxDynamicSharedMemorySize, (int)smem);

    const int grid = (Bn + EPB - 1) / EPB;
    irm_kernel<<<grid, TPB, smem>>>(ang, tgt, Kc, Re, te, vmk,
                                    W1, b1, g1, be1, W2, b2, g2, be2, W3, b3,
                                    slog, (float*)d_out, Bn);
}

// round 4
// speedup vs baseline: 1.8878x; 1.8878x over previous
#include <cuda_runtime.h>
#include <math.h>

#define TPB 256
#define EPB (TPB/4)     // 64 elements per block

typedef unsigned long long u64;

__device__ __forceinline__ u64 pk2(float x, float y) {
    u64 r; asm("mov.b64 %0, {%1,%2};" : "=l"(r) : "f"(x), "f"(y)); return r;
}
__device__ __forceinline__ void upk2(u64 v, float& x, float& y) {
    asm("mov.b64 {%0,%1}, %2;" : "=f"(x), "=f"(y) : "l"(v));
}
__device__ __forceinline__ u64 ffma2(u64 a, u64 b, u64 c) {
    u64 d; asm("fma.rn.f32x2 %0, %1, %2, %3;" : "=l"(d) : "l"(a), "l"(b), "l"(c)); return d;
}
__device__ __forceinline__ float gelu_f(float x) {
    return 0.5f * x * (1.0f + erff(x * 0.70710678118654752440f));
}

// Forward kinematics for the 7-DOF Panda chain -> 7 keypoint positions.
__device__ __forceinline__ void fk_eval(const float th[7], float kp[21]) {
    const float FR[7][9] = {
        {1,0,0,  0,1,0,   0,0,1},
        {1,0,0,  0,0,1,   0,-1,0},
        {1,0,0,  0,0,-1,  0,1,0},
        {1,0,0,  0,0,-1,  0,1,0},
        {1,0,0,  0,0,1,   0,-1,0},
        {1,0,0,  0,0,-1,  0,1,0},
        {1,0,0,  0,0,-1,  0,1,0}
    };
    const float FT[7][3] = {
        {0.f,0.f,0.333f},{0.f,0.f,0.f},{0.f,-0.316f,0.f},{0.0825f,0.f,0.f},
        {-0.0825f,0.384f,0.f},{0.f,0.f,0.f},{0.088f,0.f,0.f}
    };
    float r[9] = {1,0,0, 0,1,0, 0,0,1};
    float t[3] = {0,0,0};
    kp[0] = 0.f; kp[1] = 0.f; kp[2] = 0.f;
    int w = 3;
    #pragma unroll
    for (int i = 0; i < 7; i++) {
        float s, c; sincosf(th[i], &s, &c);
        float sr[9];
        sr[0] =  FR[i][0]*c + FR[i][1]*s;  sr[1] = -FR[i][0]*s + FR[i][1]*c;  sr[2] = FR[i][2];
        sr[3] =  FR[i][3]*c + FR[i][4]*s;  sr[4] = -FR[i][3]*s + FR[i][4]*c;  sr[5] = FR[i][5];
        sr[6] =  FR[i][6]*c + FR[i][7]*s;  sr[7] = -FR[i][6]*s + FR[i][7]*c;  sr[8] = FR[i][8];
        float nt0 = r[0]*FT[i][0] + r[1]*FT[i][1] + r[2]*FT[i][2] + t[0];
        float nt1 = r[3]*FT[i][0] + r[4]*FT[i][1] + r[5]*FT[i][2] + t[1];
        float nt2 = r[6]*FT[i][0] + r[7]*FT[i][1] + r[8]*FT[i][2] + t[2];
        float nr[9];
        #pragma unroll
        for (int a = 0; a < 3; a++)
            #pragma unroll
            for (int bq = 0; bq < 3; bq++)
                nr[a*3+bq] = r[a*3+0]*sr[bq] + r[a*3+1]*sr[3+bq] + r[a*3+2]*sr[6+bq];
        #pragma unroll
        for (int q = 0; q < 9; q++) r[q] = nr[q];
        t[0] = nt0; t[1] = nt1; t[2] = nt2;
        if (i == 1 || i == 2 || i == 3 || i == 5 || i == 6) {
            kp[w] = t[0]; kp[w+1] = t[1]; kp[w+2] = t[2]; w += 3;
        }
    }
    kp[18] = t[0] + r[2]*0.107f;
    kp[19] = t[1] + r[5]*0.107f;
    kp[20] = t[2] + r[8]*0.107f;
}

// ---- Shared memory layout (float offsets). Bank-skewed slices:
// each 32-unit slice padded to 36 floats (36 mod 32 = 4 -> quad lanes hit
// disjoint banks). W rows: 4*36 = 144 floats/row.
#define OFF_W1   0                     // 28*144 = 4032
#define OFF_W2   (OFF_W1 + 28*144)     // 128*144 = 18432
#define OFF_W3   (OFF_W2 + 128*144)    // 4*260 = 1040 (slice stride 260 = 32*8+4)
#define OFF_B1   (OFF_W3 + 4*260)      // 144 each
#define OFF_G1   (OFF_B1 + 144)
#define OFF_BE1  (OFF_G1 + 144)
#define OFF_B2   (OFF_BE1 + 144)
#define OFF_G2   (OFF_B2 + 144)
#define OFF_BE2  (OFF_G2 + 144)
#define OFF_B3   (OFF_BE2 + 144)       // 8
#define OFF_CAM  (OFF_B3 + 8)          // 64*36
#define SMEM_FLOATS (OFF_CAM + EPB*36)

__global__ void __launch_bounds__(TPB, 2)
irm_kernel(const float* __restrict__ ang, const float* __restrict__ tgt,
           const float* __restrict__ Kc,  const float* __restrict__ Re,
           const float* __restrict__ te,  const int* __restrict__ vmk,
           const float* __restrict__ W1,  const float* __restrict__ b1,
           const float* __restrict__ g1,  const float* __restrict__ be1,
           const float* __restrict__ W2,  const float* __restrict__ b2,
           const float* __restrict__ g2,  const float* __restrict__ be2,
           const float* __restrict__ W3,  const float* __restrict__ b3,
           const float* __restrict__ slog, float* __restrict__ out, int Bn)
{
    extern __shared__ float sm[];
    float* sW1  = sm + OFF_W1;
    float* sW2  = sm + OFF_W2;
    float* sW3  = sm + OFF_W3;
    float* sb1  = sm + OFF_B1;
    float* sg1  = sm + OFF_G1;
    float* sbe1 = sm + OFF_BE1;
    float* sb2  = sm + OFF_B2;
    float* sg2  = sm + OFF_G2;
    float* sbe2 = sm + OFF_BE2;
    float* sb3  = sm + OFF_B3;
    float* sCam = sm + OFF_CAM;

    const int tid = threadIdx.x;
    const int b0  = blockIdx.x * EPB;

    // weights -> skewed smem layout
    for (int i = tid; i < 28*128; i += TPB) {
        int k = i >> 7, j = i & 127;
        sW1[k*144 + (j>>5)*36 + (j&31)] = W1[i];
    }
    for (int i = tid; i < 128*128; i += TPB) {
        int k = i >> 7, j = i & 127;
        sW2[k*144 + (j>>5)*36 + (j&31)] = W2[i];
    }
    for (int i = tid; i < 1024; i += TPB) {
        int k = i >> 3, j = i & 7;
        float v = (j < 7) ? W3[k*7 + j] : 0.f;
        sW3[(k>>5)*260 + (k&31)*8 + j] = v;
    }
    if (tid < 128) {
        int o = (tid>>5)*36 + (tid&31);
        sb1[o]  = b1[tid];  sg1[o] = g1[tid];  sbe1[o] = be1[tid];
        sb2[o]  = b2[tid];  sg2[o] = g2[tid];  sbe2[o] = be2[tid];
    }
    if (tid < 8) sb3[tid] = (tid < 7) ? b3[tid] : 0.f;

    // loop-invariant per-element camera data -> smem (coalesced, once)
    for (int i = tid; i < EPB*9; i += TPB) {
        int el = i / 9, c = i - el*9;
        int bb = min(b0 + el, Bn - 1);
        sCam[el*36 + c]     = Re[(size_t)bb*9 + c];
        sCam[el*36 + 9 + c] = Kc[(size_t)bb*9 + c];
    }
    for (int i = tid; i < EPB*3; i += TPB) {
        int el = i / 3, c = i - el*3;
        int bb = min(b0 + el, Bn - 1);
        sCam[el*36 + 18 + c] = te[(size_t)bb*3 + c];
    }
    for (int i = tid; i < EPB*14; i += TPB) {
        int el = i / 14, c = i - el*14;
        int bb = min(b0 + el, Bn - 1);
        sCam[el*36 + 21 + c] = tgt[(size_t)bb*14 + c];
    }
    if (tid < EPB) {
        int bb = min(b0 + tid, Bn - 1);
        sCam[tid*36 + 35] = (vmk[bb] != 0) ? 1.f : 0.f;
    }
    __syncthreads();

    const int q  = tid & 3;            // quad lane: owns hidden units [32q, 32q+32)
    const int el = tid >> 2;
    int b = b0 + el;
    const bool valid = (b < Bn);
    if (b >= Bn) b = Bn - 1;

    const float* C = sCam + el*36;     // Rm[0..8], Km[9..17], tv[18..20], tg[21..34], vm[35]

    float th[7];
    #pragma unroll
    for (int j = 0; j < 7; j++) th[j] = ang[(size_t)b*7 + j];

    const float LO[7] = {-2.8973f,-1.7628f,-2.8973f,-3.0718f,-2.8973f,-0.0175f,-2.8973f};
    const float HI[7] = { 2.8973f, 1.7628f, 2.8973f,-0.0698f, 2.8973f, 3.7525f, 2.8973f};

    float kp[21];
    fk_eval(th, kp);

    float* outA = out + (size_t)28 * Bn;   // all_angles (4,B,7)
    float* outK = out + (size_t)56 * Bn;   // all_kp     (4,B,7,3)

    if (q == 0 && valid) {
        #pragma unroll
        for (int j = 0; j < 7; j++)  outA[(size_t)b*7 + j]  = th[j];
        #pragma unroll
        for (int j = 0; j < 21; j++) outK[(size_t)b*21 + j] = kp[j];
    }

    for (int it = 0; it < 3; it++) {
        // ---- features (smem camera data; quad-redundant compute, no gmem) ----
        float x[28];
        {
            const float vm = C[35];
            #pragma unroll
            for (int k = 0; k < 7; k++) {
                float px = kp[3*k], py = kp[3*k+1], pz = kp[3*k+2];
                float cx = C[0]*px + C[1]*py + C[2]*pz + C[18];
                float cy = C[3]*px + C[4]*py + C[5]*pz + C[19];
                float cz = C[6]*px + C[7]*py + C[8]*pz + C[20];
                float z  = fmaxf(cz, 1e-6f);
                float inv = 1.0f / z;
                float nx = cx*inv, ny = cy*inv, nz = cz*inv;
                float u = C[9]*nx  + C[10]*ny + C[11]*nz;
                float v = C[12]*nx + C[13]*ny + C[14]*nz;
                float dx = (C[21 + 2*k] - u) * vm;
                float dy = (C[22 + 2*k] - v) * vm;
                x[2*k] = dx; x[2*k+1] = dy;
                x[21+k] = sqrtf(dx*dx + dy*dy);
            }
            #pragma unroll
            for (int j = 0; j < 7; j++) x[14+j] = th[j];
        }

        // ---- GEMM1: (28)->(32 per thread) ----
        u64 acc[16];
        {
            const u64* pb1 = (const u64*)(sb1 + q*36);
            #pragma unroll
            for (int i = 0; i < 16; i++) acc[i] = pb1[i];
            const float* wbase = sW1 + q*36;
            #pragma unroll
            for (int k = 0; k < 28; k++) {
                u64 xx = pk2(x[k], x[k]);
                const ulonglong2* wrow = (const ulonglong2*)(wbase + k*144);
                #pragma unroll
                for (int i = 0; i < 8; i++) {
                    ulonglong2 w = wrow[i];
                    acc[2*i]   = ffma2(xx, w.x, acc[2*i]);
                    acc[2*i+1] = ffma2(xx, w.y, acc[2*i+1]);
                }
            }
        }

        // ---- GELU + LN1 (quad reduction) ----
        float h[32];
        {
            #pragma unroll
            for (int i = 0; i < 16; i++) upk2(acc[i], h[2*i], h[2*i+1]);
            float sum = 0.f, sq = 0.f;
            #pragma unroll 4
            for (int j = 0; j < 32; j++) {
                float a = gelu_f(h[j]);
                h[j] = a; sum += a; sq += a*a;
            }
            sum += __shfl_xor_sync(0xffffffffu, sum, 1);
            sum += __shfl_xor_sync(0xffffffffu, sum, 2);
            sq  += __shfl_xor_sync(0xffffffffu, sq, 1);
            sq  += __shfl_xor_sync(0xffffffffu, sq, 2);
            float mu   = sum * (1.f/128.f);
            float var  = sq  * (1.f/128.f) - mu*mu;
            float rstd = rsqrtf(var + 1e-5f);
            const float* g = sg1 + q*36;
            const float* e = sbe1 + q*36;
            #pragma unroll
            for (int j = 0; j < 32; j++)
                h[j] = (h[j] - mu) * rstd * g[j] + e[j];
        }

        // ---- GEMM2: (128)->(32 per thread); h via quad shuffle ----
        {
            const u64* pb2 = (const u64*)(sb2 + q*36);
            #pragma unroll
            for (int i = 0; i < 16; i++) acc[i] = pb2[i];
            const float* wbase = sW2 + q*36;
            #pragma unroll 1
            for (int o = 0; o < 4; o++) {
                #pragma unroll
                for (int j = 0; j < 32; j++) {
                    float v = __shfl_sync(0xffffffffu, h[j], o, 4);
                    u64 hh = pk2(v, v);
                    const ulonglong2* wrow = (const ulonglong2*)(wbase + (o*32 + j)*144);
                    #pragma unroll
                    for (int i = 0; i < 8; i++) {
                        ulonglong2 w = wrow[i];
                        acc[2*i]   = ffma2(hh, w.x, acc[2*i]);
                        acc[2*i+1] = ffma2(hh, w.y, acc[2*i+1]);
                    }
                }
            }
        }

        // ---- GELU + LN2 ----
        {
            #pragma unroll
            for (int i = 0; i < 16; i++) upk2(acc[i], h[2*i], h[2*i+1]);
            float sum = 0.f, sq = 0.f;
            #pragma unroll 4
            for (int j = 0; j < 32; j++) {
                float a = gelu_f(h[j]);
                h[j] = a; sum += a; sq += a*a;
            }
            sum += __shfl_xor_sync(0xffffffffu, sum, 1);
            sum += __shfl_xor_sync(0xffffffffu, sum, 2);
            sq  += __shfl_xor_sync(0xffffffffu, sq, 1);
            sq  += __shfl_xor_sync(0xffffffffu, sq, 2);
            float mu   = sum * (1.f/128.f);
            float var  = sq  * (1.f/128.f) - mu*mu;
            float rstd = rsqrtf(var + 1e-5f);
            const float* g = sg2 + q*36;
            const float* e = sbe2 + q*36;
            #pragma unroll
            for (int j = 0; j < 32; j++)
                h[j] = (h[j] - mu) * rstd * g[j] + e[j];
        }

        // ---- GEMM3: partial (32)->(7), quad reduce ----
        float a3[7] = {0,0,0,0,0,0,0};
        {
            const float* w3base = sW3 + q*260;
            #pragma unroll
            for (int j = 0; j < 32; j++) {
                float v = h[j];
                const float4* w4 = (const float4*)(w3base + j*8);
                float4 wa = w4[0], wb = w4[1];
                a3[0] += v*wa.x; a3[1] += v*wa.y; a3[2] += v*wa.z; a3[3] += v*wa.w;
                a3[4] += v*wb.x; a3[5] += v*wb.y; a3[6] += v*wb.z;
            }
        }
        #pragma unroll
        for (int c = 0; c < 7; c++) {
            a3[c] += __shfl_xor_sync(0xffffffffu, a3[c], 1);
            a3[c] += __shfl_xor_sync(0xffffffffu, a3[c], 2);
            a3[c] += sb3[c];
        }

        float ss = 1.f / (1.f + expf(-slog[it]));
        #pragma unroll
        for (int j = 0; j < 7; j++) {
            float nv = th[j] + ss * a3[j];
            th[j] = fminf(fmaxf(nv, LO[j]), HI[j]);
        }
        fk_eval(th, kp);

        const size_t w = (size_t)(it + 1);
        if (q == 0 && valid) {
            #pragma unroll
            for (int j = 0; j < 7; j++)  outA[w*(size_t)Bn*7  + (size_t)b*7  + j] = th[j];
            #pragma unroll
            for (int j = 0; j < 21; j++) outK[w*(size_t)Bn*21 + (size_t)b*21 + j] = kp[j];
        }
    }

    if (q == 0 && valid) {
        #pragma unroll
        for (int j = 0; j < 7; j++)  out[(size_t)b*7 + j] = th[j];
        #pragma unroll
        for (int j = 0; j < 21; j++) out[(size_t)7*Bn + (size_t)b*21 + j] = kp[j];
    }
}

extern "C" void kernel_launch(void* const* d_in, const int* in_sizes, int n_in,
                              void* d_out, int out_size)
{
    const float* ang  = (const float*)d_in[0];
    const float* tgt  = (const float*)d_in[1];
    const float* Kc   = (const float*)d_in[2];
    const float* Re   = (const float*)d_in[4];
    const float* te   = (const float*)d_in[5];
    const int*   vmk  = (const int*)d_in[6];
    const float* W1   = (const float*)d_in[7];
    const float* b1   = (const float*)d_in[8];
    const float* g1   = (const float*)d_in[9];
    const float* be1  = (const float*)d_in[10];
    const float* W2   = (const float*)d_in[11];
    const float* b2   = (const float*)d_in[12];
    const float* g2   = (const float*)d_in[13];
    const float* be2  = (const float*)d_in[14];
    const float* W3   = (const float*)d_in[15];
    const float* b3   = (const float*)d_in[16];
    const float* slog = (const float*)d_in[17];

    const int Bn = in_sizes[0] / 7;
    const size_t smem = (size_t)SMEM_FLOATS * sizeof(float);

    cudaFuncSetAttribute(irm_kernel, cudaFuncAttributeMaxDynamicSharedMemorySize, (int)smem);

    const int grid = (Bn + EPB - 1) / EPB;
    irm_kernel<<<grid, TPB, smem>>>(ang, tgt, Kc, Re, te, vmk,
                                    W1, b1, g1, be1, W2, b2, g2, be2, W3, b3,
                                    slog, (float*)d_out, Bn);
}

// round 6
// speedup vs baseline: 5.4572x; 2.8908x over previous
#include <cuda_runtime.h>
#include <math.h>

#define TPB 256

typedef unsigned long long u64;

__device__ __forceinline__ u64 pk2(float x, float y) {
    u64 r; asm("mov.b64 %0, {%1,%2};" : "=l"(r) : "f"(x), "f"(y)); return r;
}
__device__ __forceinline__ void upk2(u64 v, float& x, float& y) {
    asm("mov.b64 {%0,%1}, %2;" : "=f"(x), "=f"(y) : "l"(v));
}
__device__ __forceinline__ u64 ffma2(u64 a, u64 b, u64 c) {
    u64 d; asm("fma.rn.f32x2 %0, %1, %2, %3;" : "=l"(d) : "l"(a), "l"(b), "l"(c)); return d;
}
__device__ __forceinline__ float gelu_f(float x) {
    return 0.5f * x * (1.0f + erff(x * 0.70710678118654752440f));
}

// FK for the 7-DOF Panda chain -> 7 keypoints
__device__ __forceinline__ void fk_eval(const float th[7], float kp[21]) {
    const float FR[7][9] = {
        {1,0,0,  0,1,0,   0,0,1},
        {1,0,0,  0,0,1,   0,-1,0},
        {1,0,0,  0,0,-1,  0,1,0},
        {1,0,0,  0,0,-1,  0,1,0},
        {1,0,0,  0,0,1,   0,-1,0},
        {1,0,0,  0,0,-1,  0,1,0},
        {1,0,0,  0,0,-1,  0,1,0}
    };
    const float FT[7][3] = {
        {0.f,0.f,0.333f},{0.f,0.f,0.f},{0.f,-0.316f,0.f},{0.0825f,0.f,0.f},
        {-0.0825f,0.384f,0.f},{0.f,0.f,0.f},{0.088f,0.f,0.f}
    };
    float r[9] = {1,0,0, 0,1,0, 0,0,1};
    float t[3] = {0,0,0};
    kp[0] = 0.f; kp[1] = 0.f; kp[2] = 0.f;
    int w = 3;
    #pragma unroll
    for (int i = 0; i < 7; i++) {
        float s, c; __sincosf(th[i], &s, &c);
        float sr[9];
        sr[0] =  FR[i][0]*c + FR[i][1]*s;  sr[1] = -FR[i][0]*s + FR[i][1]*c;  sr[2] = FR[i][2];
        sr[3] =  FR[i][3]*c + FR[i][4]*s;  sr[4] = -FR[i][3]*s + FR[i][4]*c;  sr[5] = FR[i][5];
        sr[6] =  FR[i][6]*c + FR[i][7]*s;  sr[7] = -FR[i][6]*s + FR[i][7]*c;  sr[8] = FR[i][8];
        float nt0 = r[0]*FT[i][0] + r[1]*FT[i][1] + r[2]*FT[i][2] + t[0];
        float nt1 = r[3]*FT[i][0] + r[4]*FT[i][1] + r[5]*FT[i][2] + t[1];
        float nt2 = r[6]*FT[i][0] + r[7]*FT[i][1] + r[8]*FT[i][2] + t[2];
        float nr[9];
        #pragma unroll
        for (int a = 0; a < 3; a++)
            #pragma unroll
            for (int bq = 0; bq < 3; bq++)
                nr[a*3+bq] = r[a*3+0]*sr[bq] + r[a*3+1]*sr[3+bq] + r[a*3+2]*sr[6+bq];
        #pragma unroll
        for (int q = 0; q < 9; q++) r[q] = nr[q];
        t[0] = nt0; t[1] = nt1; t[2] = nt2;
        if (i == 1 || i == 2 || i == 3 || i == 5 || i == 6) {
            kp[w] = t[0]; kp[w+1] = t[1]; kp[w+2] = t[2]; w += 3;
        }
    }
    kp[18] = t[0] + r[2]*0.107f;
    kp[19] = t[1] + r[5]*0.107f;
    kp[20] = t[2] + r[8]*0.107f;
}

// ---- smem float offsets ----
#define OFF_W1    0                    // 28*128 raw
#define OFF_GW2   3584                 // 128*128 (g1-scaled W2)
#define OFF_GW3   (OFF_GW2 + 16384)    // 128*8 (g2-scaled W3, padded)
#define OFF_B1    (OFF_GW3 + 1024)     // 128
#define OFF_G1    (OFF_B1 + 128)
#define OFF_BE1   (OFF_G1 + 128)
#define OFF_A2    (OFF_BE1 + 128)      // 128: sum_k g1[k] W2[k,u]
#define OFF_CB2   (OFF_A2 + 128)       // 128: sum_k be1[k] W2[k,u] + b2[u]
#define OFF_A3    (OFF_CB2 + 128)      // 8
#define OFF_CB3   (OFF_A3 + 8)         // 8
#define OFF_H     (OFF_CB3 + 8)        // fp32 staging: 128 * TPB
#define SMEM_BYTES ((OFF_H + 128 * TPB) * 4)

__global__ void __launch_bounds__(TPB, 1)
irm_kernel(const float* __restrict__ ang, const float* __restrict__ tgt,
           const float* __restrict__ Kc,  const float* __restrict__ Re,
           const float* __restrict__ te,  const int* __restrict__ vmk,
           const float* __restrict__ W1,  const float* __restrict__ b1,
           const float* __restrict__ g1,  const float* __restrict__ be1,
           const float* __restrict__ W2,  const float* __restrict__ b2,
           const float* __restrict__ g2,  const float* __restrict__ be2,
           const float* __restrict__ W3,  const float* __restrict__ b3,
           const float* __restrict__ slog, float* __restrict__ out, int Bn)
{
    extern __shared__ float sm[];
    float* sW1  = sm + OFF_W1;
    float* sGW2 = sm + OFF_GW2;
    float* sGW3 = sm + OFF_GW3;
    float* sb1  = sm + OFF_B1;
    float* sg1  = sm + OFF_G1;
    float* sbe1 = sm + OFF_BE1;
    float* sA2  = sm + OFF_A2;
    float* sCB2 = sm + OFF_CB2;
    float* sA3  = sm + OFF_A3;
    float* sCB3 = sm + OFF_CB3;
    float* sH   = sm + OFF_H;

    const int tid = threadIdx.x;

    // ---- phase 1: raw weight loads + GW3 (g2-scaled W3) ----
    for (int i = tid; i < 3584;  i += TPB) sW1[i] = W1[i];
    for (int i = tid; i < 16384; i += TPB) sGW2[i] = W2[i];   // raw for now
    for (int i = tid; i < 1024;  i += TPB) {
        int k = i >> 3, j = i & 7;
        sGW3[i] = (j < 7) ? g2[k] * W3[k*7 + j] : 0.f;
    }
    if (tid < 128) {
        sb1[tid] = b1[tid]; sg1[tid] = g1[tid]; sbe1[tid] = be1[tid];
    }
    __syncthreads();

    // ---- phase 2: fold LN1 into layer-2 constants; LN2 constants ----
    if (tid < 128) {
        float a2 = 0.f, cb2 = 0.f;
        for (int k = 0; k < 128; k++) {
            float w = sGW2[k*128 + tid];
            a2  += sg1[k]  * w;
            cb2 += sbe1[k] * w;
        }
        sA2[tid]  = a2;
        sCB2[tid] = cb2 + b2[tid];
    } else if (tid < 136) {
        int c = tid - 128;
        float a3 = 0.f, cb3 = 0.f;
        if (c < 7) {
            for (int k = 0; k < 128; k++) {
                a3  += sGW3[k*8 + c];
                cb3 += be2[k] * W3[k*7 + c];
            }
            cb3 += b3[c];
        }
        sA3[c]  = a3;
        sCB3[c] = cb3;
    }
    __syncthreads();

    // ---- phase 3: scale W2 in place by g1 ----
    for (int i = tid; i < 16384; i += TPB) sGW2[i] *= sg1[i >> 7];
    __syncthreads();

    const int b = blockIdx.x * TPB + tid;
    if (b >= Bn) return;

    float th[7];
    #pragma unroll
    for (int j = 0; j < 7; j++) th[j] = ang[(size_t)b*7 + j];
    const float vm = (vmk[b] != 0) ? 1.f : 0.f;

    const float LO[7] = {-2.8973f,-1.7628f,-2.8973f,-3.0718f,-2.8973f,-0.0175f,-2.8973f};
    const float HI[7] = { 2.8973f, 1.7628f, 2.8973f,-0.0698f, 2.8973f, 3.7525f, 2.8973f};

    float kp[21];
    fk_eval(th, kp);

    float* outA = out + (size_t)28 * Bn;   // all_angles (4,B,7)
    float* outK = out + (size_t)56 * Bn;   // all_kp     (4,B,7,3)

    #pragma unroll
    for (int j = 0; j < 7; j++)  outA[(size_t)b*7 + j]  = th[j];
    #pragma unroll
    for (int j = 0; j < 21; j++) outK[(size_t)b*21 + j] = kp[j];

    for (int it = 0; it < 3; it++) {
        // ---- features ----
        float x[28];
        {
            float Rm[9], Km[9], tv[3];
            #pragma unroll
            for (int j = 0; j < 9; j++) { Rm[j] = Re[(size_t)b*9 + j]; Km[j] = Kc[(size_t)b*9 + j]; }
            #pragma unroll
            for (int j = 0; j < 3; j++) tv[j] = te[(size_t)b*3 + j];
            #pragma unroll
            for (int k = 0; k < 7; k++) {
                float px = kp[3*k], py = kp[3*k+1], pz = kp[3*k+2];
                float cx = Rm[0]*px + Rm[1]*py + Rm[2]*pz + tv[0];
                float cy = Rm[3]*px + Rm[4]*py + Rm[5]*pz + tv[1];
                float cz = Rm[6]*px + Rm[7]*py + Rm[8]*pz + tv[2];
                float z  = fmaxf(cz, 1e-6f);
                float inv = 1.0f / z;
                float nx = cx*inv, ny = cy*inv, nz = cz*inv;
                float u = Km[0]*nx + Km[1]*ny + Km[2]*nz;
                float v = Km[3]*nx + Km[4]*ny + Km[5]*nz;
                float dx = (tgt[(size_t)b*14 + 2*k]   - u) * vm;
                float dy = (tgt[(size_t)b*14 + 2*k+1] - v) * vm;
                x[2*k] = dx; x[2*k+1] = dy;
                x[21+k] = sqrtf(dx*dx + dy*dy);
            }
            #pragma unroll
            for (int j = 0; j < 7; j++) x[14+j] = th[j];
        }

        // ---- layer 1: 4 passes of 32 units; stage gelu(h1) as fp32 ----
        float sum1 = 0.f, sq1 = 0.f;
        #pragma unroll 1
        for (int p = 0; p < 4; p++) {
            u64 acc[16];
            const u64* pb1 = (const u64*)sb1 + p*16;
            #pragma unroll
            for (int i = 0; i < 16; i++) acc[i] = pb1[i];
            const float* wbase = sW1 + p*32;
            #pragma unroll 4
            for (int k = 0; k < 28; k++) {
                u64 xx = pk2(x[k], x[k]);
                const ulonglong2* wrow = (const ulonglong2*)(wbase + k*128);
                #pragma unroll
                for (int i = 0; i < 8; i++) {
                    ulonglong2 w = wrow[i];
                    acc[2*i]   = ffma2(xx, w.x, acc[2*i]);
                    acc[2*i+1] = ffma2(xx, w.y, acc[2*i+1]);
                }
            }
            #pragma unroll
            for (int i = 0; i < 16; i++) {
                float a0, a1; upk2(acc[i], a0, a1);
                float h0 = gelu_f(a0), h1v = gelu_f(a1);
                sum1 += h0 + h1v;
                sq1  += h0*h0 + h1v*h1v;
                sH[(p*32 + 2*i)*TPB + tid]     = h0;
                sH[(p*32 + 2*i + 1)*TPB + tid] = h1v;
            }
        }
        float mu1   = sum1 * (1.f/128.f);
        float var1  = sq1  * (1.f/128.f) - mu1*mu1;
        float rstd1 = rsqrtf(var1 + 1e-5f);
        float m1    = -mu1 * rstd1;

        // ---- layer 2: 4 passes; T = h1 @ GW2; pre2 = rstd1*T + m1*A2 + CB2 ----
        float sum2 = 0.f, sq2 = 0.f;
        float S[7] = {0,0,0,0,0,0,0};
        #pragma unroll 1
        for (int p = 0; p < 4; p++) {
            u64 acc[16];
            #pragma unroll
            for (int i = 0; i < 16; i++) acc[i] = pk2(0.f, 0.f);
            const float* wbase = sGW2 + p*32;
            #pragma unroll 2
            for (int j = 0; j < 128; j++) {
                float hv = sH[j*TPB + tid];
                u64 hh = pk2(hv, hv);
                const ulonglong2* wrow = (const ulonglong2*)(wbase + j*128);
                #pragma unroll
                for (int i = 0; i < 8; i++) {
                    ulonglong2 w = wrow[i];
                    acc[2*i]   = ffma2(hh, w.x, acc[2*i]);
                    acc[2*i+1] = ffma2(hh, w.y, acc[2*i+1]);
                }
            }
            // epilogue: LN1 constants, gelu, stats, fused GEMM3 partials
            #pragma unroll
            for (int i = 0; i < 16; i++) {
                float t0, t1; upk2(acc[i], t0, t1);
                int u = p*32 + 2*i;
                float2 a2 = *(const float2*)(sA2 + u);
                float2 cb = *(const float2*)(sCB2 + u);
                float pre0 = fmaf(rstd1, t0, fmaf(m1, a2.x, cb.x));
                float pre1 = fmaf(rstd1, t1, fmaf(m1, a2.y, cb.y));
                float h0 = gelu_f(pre0), h1v = gelu_f(pre1);
                sum2 += h0 + h1v;
                sq2  += h0*h0 + h1v*h1v;
                const float4* g0  = (const float4*)(sGW3 + u*8);
                const float4* g1r = (const float4*)(sGW3 + (u+1)*8);
                float4 ga = g0[0], gb = g0[1], gc = g1r[0], gd = g1r[1];
                S[0] = fmaf(h0, ga.x, fmaf(h1v, gc.x, S[0]));
                S[1] = fmaf(h0, ga.y, fmaf(h1v, gc.y, S[1]));
                S[2] = fmaf(h0, ga.z, fmaf(h1v, gc.z, S[2]));
                S[3] = fmaf(h0, ga.w, fmaf(h1v, gc.w, S[3]));
                S[4] = fmaf(h0, gb.x, fmaf(h1v, gd.x, S[4]));
                S[5] = fmaf(h0, gb.y, fmaf(h1v, gd.y, S[5]));
                S[6] = fmaf(h0, gb.z, fmaf(h1v, gd.z, S[6]));
            }
        }
        float mu2   = sum2 * (1.f/128.f);
        float var2  = sq2  * (1.f/128.f) - mu2*mu2;
        float rstd2 = rsqrtf(var2 + 1e-5f);
        float m2    = -mu2 * rstd2;

        float ss = 1.f / (1.f + expf(-slog[it]));
        #pragma unroll
        for (int j = 0; j < 7; j++) {
            float delta = fmaf(rstd2, S[j], fmaf(m2, sA3[j], sCB3[j]));
            float nv = th[j] + ss * delta;
            th[j] = fminf(fmaxf(nv, LO[j]), HI[j]);
        }
        fk_eval(th, kp);

        const size_t w = (size_t)(it + 1);
        #pragma unroll
        for (int j = 0; j < 7; j++)  outA[w*(size_t)Bn*7  + (size_t)b*7  + j] = th[j];
        #pragma unroll
        for (int j = 0; j < 21; j++) outK[w*(size_t)Bn*21 + (size_t)b*21 + j] = kp[j];
    }

    #pragma unroll
    for (int j = 0; j < 7; j++)  out[(size_t)b*7 + j] = th[j];
    #pragma unroll
    for (int j = 0; j < 21; j++) out[(size_t)7*Bn + (size_t)b*21 + j] = kp[j];
}

extern "C" void kernel_launch(void* const* d_in, const int* in_sizes, int n_in,
                              void* d_out, int out_size)
{
    const float* ang  = (const float*)d_in[0];
    const float* tgt  = (const float*)d_in[1];
    const float* Kc   = (const float*)d_in[2];
    const float* Re   = (const float*)d_in[4];
    const float* te   = (const float*)d_in[5];
    const int*   vmk  = (const int*)d_in[6];
    const float* W1   = (const float*)d_in[7];
    const float* b1   = (const float*)d_in[8];
    const float* g1   = (const float*)d_in[9];
    const float* be1  = (const float*)d_in[10];
    const float* W2   = (const float*)d_in[11];
    const float* b2   = (const float*)d_in[12];
    const float* g2   = (const float*)d_in[13];
    const float* be2  = (const float*)d_in[14];
    const float* W3   = (const float*)d_in[15];
    const float* b3   = (const float*)d_in[16];
    const float* slog = (const float*)d_in[17];

    const int Bn = in_sizes[0] / 7;
    const size_t smem = (size_t)SMEM_BYTES;

    cudaFuncSetAttribute(irm_kernel, cudaFuncAttributeMaxDynamicSharedMemorySize, (int)smem);

    const int grid = (Bn + TPB - 1) / TPB;
    irm_kernel<<<grid, TPB, smem>>>(ang, tgt, Kc, Re, te, vmk,
                                    W1, b1, g1, be1, W2, b2, g2, be2, W3, b3,
                                    slog, (float*)d_out, Bn);
}

// round 7
// speedup vs baseline: 5.4941x; 1.0068x over previous
#include <cuda_runtime.h>
#include <math.h>

#define TPB 256

typedef unsigned long long u64;

__device__ __forceinline__ u64 pk2(float x, float y) {
    u64 r; asm("mov.b64 %0, {%1,%2};" : "=l"(r) : "f"(x), "f"(y)); return r;
}
__device__ __forceinline__ void upk2(u64 v, float& x, float& y) {
    asm("mov.b64 {%0,%1}, %2;" : "=f"(x), "=f"(y) : "l"(v));
}
__device__ __forceinline__ u64 ffma2(u64 a, u64 b, u64 c) {
    u64 d; asm("fma.rn.f32x2 %0, %1, %2, %3;" : "=l"(d) : "l"(a), "l"(b), "l"(c)); return d;
}
__device__ __forceinline__ float gelu_f(float x) {
    return 0.5f * x * (1.0f + erff(x * 0.70710678118654752440f));
}

// FK for the 7-DOF Panda chain -> 7 keypoints
__device__ __forceinline__ void fk_eval(const float th[7], float kp[21]) {
    const float FR[7][9] = {
        {1,0,0,  0,1,0,   0,0,1},
        {1,0,0,  0,0,1,   0,-1,0},
        {1,0,0,  0,0,-1,  0,1,0},
        {1,0,0,  0,0,-1,  0,1,0},
        {1,0,0,  0,0,1,   0,-1,0},
        {1,0,0,  0,0,-1,  0,1,0},
        {1,0,0,  0,0,-1,  0,1,0}
    };
    const float FT[7][3] = {
        {0.f,0.f,0.333f},{0.f,0.f,0.f},{0.f,-0.316f,0.f},{0.0825f,0.f,0.f},
        {-0.0825f,0.384f,0.f},{0.f,0.f,0.f},{0.088f,0.f,0.f}
    };
    float r[9] = {1,0,0, 0,1,0, 0,0,1};
    float t[3] = {0,0,0};
    kp[0] = 0.f; kp[1] = 0.f; kp[2] = 0.f;
    int w = 3;
    #pragma unroll
    for (int i = 0; i < 7; i++) {
        float s, c; __sincosf(th[i], &s, &c);
        float sr[9];
        sr[0] =  FR[i][0]*c + FR[i][1]*s;  sr[1] = -FR[i][0]*s + FR[i][1]*c;  sr[2] = FR[i][2];
        sr[3] =  FR[i][3]*c + FR[i][4]*s;  sr[4] = -FR[i][3]*s + FR[i][4]*c;  sr[5] = FR[i][5];
        sr[6] =  FR[i][6]*c + FR[i][7]*s;  sr[7] = -FR[i][6]*s + FR[i][7]*c;  sr[8] = FR[i][8];
        float nt0 = r[0]*FT[i][0] + r[1]*FT[i][1] + r[2]*FT[i][2] + t[0];
        float nt1 = r[3]*FT[i][0] + r[4]*FT[i][1] + r[5]*FT[i][2] + t[1];
        float nt2 = r[6]*FT[i][0] + r[7]*FT[i][1] + r[8]*FT[i][2] + t[2];
        float nr[9];
        #pragma unroll
        for (int a = 0; a < 3; a++)
            #pragma unroll
            for (int bq = 0; bq < 3; bq++)
                nr[a*3+bq] = r[a*3+0]*sr[bq] + r[a*3+1]*sr[3+bq] + r[a*3+2]*sr[6+bq];
        #pragma unroll
        for (int q = 0; q < 9; q++) r[q] = nr[q];
        t[0] = nt0; t[1] = nt1; t[2] = nt2;
        if (i == 1 || i == 2 || i == 3 || i == 5 || i == 6) {
            kp[w] = t[0]; kp[w+1] = t[1]; kp[w+2] = t[2]; w += 3;
        }
    }
    kp[18] = t[0] + r[2]*0.107f;
    kp[19] = t[1] + r[5]*0.107f;
    kp[20] = t[2] + r[8]*0.107f;
}

// ---- smem float offsets ----
#define OFF_W1    0                    // 28*128 raw
#define OFF_GW2   3584                 // 128*128 (g1-scaled W2)
#define OFF_GW3   (OFF_GW2 + 16384)    // 128*8 (g2-scaled W3, padded)
#define OFF_B1    (OFF_GW3 + 1024)     // 128
#define OFF_G1    (OFF_B1 + 128)
#define OFF_BE1   (OFF_G1 + 128)
#define OFF_A2    (OFF_BE1 + 128)      // 128
#define OFF_CB2   (OFF_A2 + 128)       // 128
#define OFF_A3    (OFF_CB2 + 128)      // 8
#define OFF_CB3   (OFF_A3 + 8)         // 8
#define OFF_H     (OFF_CB3 + 8)        // fp32 staging as float2: 64 pairs * TPB
#define SMEM_BYTES ((OFF_H + 128 * TPB) * 4)

__global__ void __launch_bounds__(TPB, 1)
irm_kernel(const float* __restrict__ ang, const float* __restrict__ tgt,
           const float* __restrict__ Kc,  const float* __restrict__ Re,
           const float* __restrict__ te,  const int* __restrict__ vmk,
           const float* __restrict__ W1,  const float* __restrict__ b1,
           const float* __restrict__ g1,  const float* __restrict__ be1,
           const float* __restrict__ W2,  const float* __restrict__ b2,
           const float* __restrict__ g2,  const float* __restrict__ be2,
           const float* __restrict__ W3,  const float* __restrict__ b3,
           const float* __restrict__ slog, float* __restrict__ out, int Bn)
{
    extern __shared__ float sm[];
    float* sW1  = sm + OFF_W1;
    float* sGW2 = sm + OFF_GW2;
    float* sGW3 = sm + OFF_GW3;
    float* sb1  = sm + OFF_B1;
    float* sg1  = sm + OFF_G1;
    float* sbe1 = sm + OFF_BE1;
    float* sA2  = sm + OFF_A2;
    float* sCB2 = sm + OFF_CB2;
    float* sA3  = sm + OFF_A3;
    float* sCB3 = sm + OFF_CB3;
    float2* sH2 = (float2*)(sm + OFF_H);   // [64 pairs][TPB]

    const int tid = threadIdx.x;

    // ---- phase 1: raw weight loads + GW3 (g2-scaled W3) ----
    for (int i = tid; i < 3584;  i += TPB) sW1[i] = W1[i];
    for (int i = tid; i < 16384; i += TPB) sGW2[i] = W2[i];   // raw for now
    for (int i = tid; i < 1024;  i += TPB) {
        int k = i >> 3, j = i & 7;
        sGW3[i] = (j < 7) ? g2[k] * W3[k*7 + j] : 0.f;
    }
    if (tid < 128) {
        sb1[tid] = b1[tid]; sg1[tid] = g1[tid]; sbe1[tid] = be1[tid];
    }
    __syncthreads();

    // ---- phase 2: fold LN1 into layer-2 constants; LN2 constants ----
    if (tid < 128) {
        float a2 = 0.f, cb2 = 0.f;
        for (int k = 0; k < 128; k++) {
            float w = sGW2[k*128 + tid];
            a2  += sg1[k]  * w;
            cb2 += sbe1[k] * w;
        }
        sA2[tid]  = a2;
        sCB2[tid] = cb2 + b2[tid];
    } else if (tid < 136) {
        int c = tid - 128;
        float a3 = 0.f, cb3 = 0.f;
        if (c < 7) {
            for (int k = 0; k < 128; k++) {
                a3  += sGW3[k*8 + c];
                cb3 += be2[k] * W3[k*7 + c];
            }
            cb3 += b3[c];
        }
        sA3[c]  = a3;
        sCB3[c] = cb3;
    }
    __syncthreads();

    // ---- phase 3: scale W2 in place by g1 ----
    for (int i = tid; i < 16384; i += TPB) sGW2[i] *= sg1[i >> 7];
    __syncthreads();

    const int b = blockIdx.x * TPB + tid;
    if (b >= Bn) return;

    // ---- loop-invariant per-element data -> persistent registers ----
    float th[7];
    #pragma unroll
    for (int j = 0; j < 7; j++) th[j] = ang[(size_t)b*7 + j];
    float Rm[9], Km[6], tv[3], tg[14];
    #pragma unroll
    for (int j = 0; j < 9; j++) Rm[j] = Re[(size_t)b*9 + j];
    #pragma unroll
    for (int j = 0; j < 6; j++) Km[j] = Kc[(size_t)b*9 + j];   // rows 0,1 only
    #pragma unroll
    for (int j = 0; j < 3; j++) tv[j] = te[(size_t)b*3 + j];
    #pragma unroll
    for (int j = 0; j < 14; j++) tg[j] = tgt[(size_t)b*14 + j];
    const float vm = (vmk[b] != 0) ? 1.f : 0.f;
    float ssv[3];
    #pragma unroll
    for (int j = 0; j < 3; j++) ssv[j] = 1.f / (1.f + expf(-slog[j]));

    const float LO[7] = {-2.8973f,-1.7628f,-2.8973f,-3.0718f,-2.8973f,-0.0175f,-2.8973f};
    const float HI[7] = { 2.8973f, 1.7628f, 2.8973f,-0.0698f, 2.8973f, 3.7525f, 2.8973f};

    float kp[21];
    fk_eval(th, kp);

    float* outA = out + (size_t)28 * Bn;   // all_angles (4,B,7)
    float* outK = out + (size_t)56 * Bn;   // all_kp     (4,B,7,3)

    #pragma unroll
    for (int j = 0; j < 7; j++)  outA[(size_t)b*7 + j]  = th[j];
    #pragma unroll
    for (int j = 0; j < 21; j++) outK[(size_t)b*21 + j] = kp[j];

    for (int it = 0; it < 3; it++) {
        // ---- features (all-register) ----
        float x[28];
        {
            #pragma unroll
            for (int k = 0; k < 7; k++) {
                float px = kp[3*k], py = kp[3*k+1], pz = kp[3*k+2];
                float cx = Rm[0]*px + Rm[1]*py + Rm[2]*pz + tv[0];
                float cy = Rm[3]*px + Rm[4]*py + Rm[5]*pz + tv[1];
                float cz = Rm[6]*px + Rm[7]*py + Rm[8]*pz + tv[2];
                float z  = fmaxf(cz, 1e-6f);
                float inv = 1.0f / z;
                float nx = cx*inv, ny = cy*inv, nz = cz*inv;
                float u = Km[0]*nx + Km[1]*ny + Km[2]*nz;
                float v = Km[3]*nx + Km[4]*ny + Km[5]*nz;
                float dx = (tg[2*k]   - u) * vm;
                float dy = (tg[2*k+1] - v) * vm;
                x[2*k] = dx; x[2*k+1] = dy;
                x[21+k] = sqrtf(dx*dx + dy*dy);
            }
            #pragma unroll
            for (int j = 0; j < 7; j++) x[14+j] = th[j];
        }

        // ---- layer 1: 2 passes of 64 units; stage gelu(h1) as fp32 pairs ----
        float sum1 = 0.f, sq1 = 0.f;
        #pragma unroll 1
        for (int p = 0; p < 2; p++) {
            u64 acc[32];
            const u64* pb1 = (const u64*)sb1 + p*32;
            #pragma unroll
            for (int i = 0; i < 32; i++) acc[i] = pb1[i];
            const float* wbase = sW1 + p*64;
            #pragma unroll 2
            for (int k = 0; k < 28; k++) {
                u64 xx = pk2(x[k], x[k]);
                const ulonglong2* wrow = (const ulonglong2*)(wbase + k*128);
                #pragma unroll
                for (int i = 0; i < 16; i++) {
                    ulonglong2 w = wrow[i];
                    acc[2*i]   = ffma2(xx, w.x, acc[2*i]);
                    acc[2*i+1] = ffma2(xx, w.y, acc[2*i+1]);
                }
            }
            #pragma unroll
            for (int i = 0; i < 32; i++) {
                float a0, a1; upk2(acc[i], a0, a1);
                float h0 = gelu_f(a0), h1v = gelu_f(a1);
                sum1 += h0 + h1v;
                sq1  += h0*h0 + h1v*h1v;
                sH2[(p*32 + i)*TPB + tid] = make_float2(h0, h1v);
            }
        }
        float mu1   = sum1 * (1.f/128.f);
        float var1  = sq1  * (1.f/128.f) - mu1*mu1;
        float rstd1 = rsqrtf(var1 + 1e-5f);
        float m1    = -mu1 * rstd1;

        // ---- layer 2: 2 passes of 64 units; pre2 = rstd1*T + m1*A2 + CB2 ----
        float sum2 = 0.f, sq2 = 0.f;
        float S[7] = {0,0,0,0,0,0,0};
        #pragma unroll 1
        for (int p = 0; p < 2; p++) {
            u64 acc[32];
            #pragma unroll
            for (int i = 0; i < 32; i++) acc[i] = pk2(0.f, 0.f);
            const float* wbase = sGW2 + p*64;
            #pragma unroll 2
            for (int j2 = 0; j2 < 64; j2++) {
                float2 hv = sH2[j2*TPB + tid];
                u64 hh0 = pk2(hv.x, hv.x);
                u64 hh1 = pk2(hv.y, hv.y);
                const ulonglong2* w0 = (const ulonglong2*)(wbase + (2*j2)*128);
                const ulonglong2* w1 = (const ulonglong2*)(wbase + (2*j2+1)*128);
                #pragma unroll
                for (int i = 0; i < 16; i++) {
                    ulonglong2 wa = w0[i];
                    acc[2*i]   = ffma2(hh0, wa.x, acc[2*i]);
                    acc[2*i+1] = ffma2(hh0, wa.y, acc[2*i+1]);
                }
                #pragma unroll
                for (int i = 0; i < 16; i++) {
                    ulonglong2 wb = w1[i];
                    acc[2*i]   = ffma2(hh1, wb.x, acc[2*i]);
                    acc[2*i+1] = ffma2(hh1, wb.y, acc[2*i+1]);
                }
            }
            // epilogue: LN1 constants, gelu, stats, fused GEMM3 partials
            #pragma unroll
            for (int i = 0; i < 32; i++) {
                float t0, t1; upk2(acc[i], t0, t1);
                int u = p*64 + 2*i;
                float2 a2 = *(const float2*)(sA2 + u);
                float2 cb = *(const float2*)(sCB2 + u);
                float pre0 = fmaf(rstd1, t0, fmaf(m1, a2.x, cb.x));
                float pre1 = fmaf(rstd1, t1, fmaf(m1, a2.y, cb.y));
                float h0 = gelu_f(pre0), h1v = gelu_f(pre1);
                sum2 += h0 + h1v;
                sq2  += h0*h0 + h1v*h1v;
                const float4* g0  = (const float4*)(sGW3 + u*8);
                const float4* g1r = (const float4*)(sGW3 + (u+1)*8);
                float4 ga = g0[0], gb = g0[1], gc = g1r[0], gd = g1r[1];
                S[0] = fmaf(h0, ga.x, fmaf(h1v, gc.x, S[0]));
                S[1] = fmaf(h0, ga.y, fmaf(h1v, gc.y, S[1]));
                S[2] = fmaf(h0, ga.z, fmaf(h1v, gc.z, S[2]));
                S[3] = fmaf(h0, ga.w, fmaf(h1v, gc.w, S[3]));
                S[4] = fmaf(h0, gb.x, fmaf(h1v, gd.x, S[4]));
                S[5] = fmaf(h0, gb.y, fmaf(h1v, gd.y, S[5]));
                S[6] = fmaf(h0, gb.z, fmaf(h1v, gd.z, S[6]));
            }
        }
        float mu2   = sum2 * (1.f/128.f);
        float var2  = sq2  * (1.f/128.f) - mu2*mu2;
        float rstd2 = rsqrtf(var2 + 1e-5f);
        float m2    = -mu2 * rstd2;

        float ss = ssv[it];
        #pragma unroll
        for (int j = 0; j < 7; j++) {
            float delta = fmaf(rstd2, S[j], fmaf(m2, sA3[j], sCB3[j]));
            float nv = th[j] + ss * delta;
            th[j] = fminf(fmaxf(nv, LO[j]), HI[j]);
        }
        fk_eval(th, kp);

        const size_t w = (size_t)(it + 1);
        #pragma unroll
        for (int j = 0; j < 7; j++)  outA[w*(size_t)Bn*7  + (size_t)b*7  + j] = th[j];
        #pragma unroll
        for (int j = 0; j < 21; j++) outK[w*(size_t)Bn*21 + (size_t)b*21 + j] = kp[j];
    }

    #pragma unroll
    for (int j = 0; j < 7; j++)  out[(size_t)b*7 + j] = th[j];
    #pragma unroll
    for (int j = 0; j < 21; j++) out[(size_t)7*Bn + (size_t)b*21 + j] = kp[j];
}

extern "C" void kernel_launch(void* const* d_in, const int* in_sizes, int n_in,
                              void* d_out, int out_size)
{
    const float* ang  = (const float*)d_in[0];
    const float* tgt  = (const float*)d_in[1];
    const float* Kc   = (const float*)d_in[2];
    const float* Re   = (const float*)d_in[4];
    const float* te   = (const float*)d_in[5];
    const int*   vmk  = (const int*)d_in[6];
    const float* W1   = (const float*)d_in[7];
    const float* b1   = (const float*)d_in[8];
    const float* g1   = (const float*)d_in[9];
    const float* be1  = (const float*)d_in[10];
    const float* W2   = (const float*)d_in[11];
    const float* b2   = (const float*)d_in[12];
    const float* g2   = (const float*)d_in[13];
    const float* be2  = (const float*)d_in[14];
    const float* W3   = (const float*)d_in[15];
    const float* b3   = (const float*)d_in[16];
    const float* slog = (const float*)d_in[17];

    const int Bn = in_sizes[0] / 7;
    const size_t smem = (size_t)SMEM_BYTES;

    cudaFuncSetAttribute(irm_kernel, cudaFuncAttributeMaxDynamicSharedMemorySize, (int)smem);

    const int grid = (Bn + TPB - 1) / TPB;
    irm_kernel<<<grid, TPB, smem>>>(ang, tgt, Kc, Re, te, vmk,
                                    W1, b1, g1, be1, W2, b2, g2, be2, W3, b3,
                                    slog, (float*)d_out, Bn);
}